// round 12
// baseline (speedup 1.0000x reference)
#include <cuda_runtime.h>

// out[row, :] = x[row, :] - sum(x[row, :])
// x: [R, 512] fp32, R = 8*8192 = 65536. HBM-bound (268 MB stream, ~7.5 TB/s
// effective). Final form: one warp per row, 256-thr blocks (best measured grid
// shape), 256-bit vector loads/stores (2 LDG.256 + 2 STG.256 per lane = minimal
// LSU issue count). L2 eviction hints measured neutral -> omitted.

static constexpr int D = 512;
static constexpr int WARPS_PER_BLOCK = 8;

struct f8 { float v[8]; };

__device__ __forceinline__ f8 ldg256(const float* p) {
    f8 r;
    asm volatile(
        "ld.global.v8.b32 {%0,%1,%2,%3,%4,%5,%6,%7}, [%8];"
        : "=f"(r.v[0]), "=f"(r.v[1]), "=f"(r.v[2]), "=f"(r.v[3]),
          "=f"(r.v[4]), "=f"(r.v[5]), "=f"(r.v[6]), "=f"(r.v[7])
        : "l"(p));
    return r;
}

__device__ __forceinline__ void stg256(float* p, const f8& r) {
    asm volatile(
        "st.global.v8.b32 [%0], {%1,%2,%3,%4,%5,%6,%7,%8};"
        :: "l"(p),
           "f"(r.v[0]), "f"(r.v[1]), "f"(r.v[2]), "f"(r.v[3]),
           "f"(r.v[4]), "f"(r.v[5]), "f"(r.v[6]), "f"(r.v[7])
        : "memory");
}

__global__ void __launch_bounds__(WARPS_PER_BLOCK * 32)
neg_sum_add_kernel(const float* __restrict__ x, float* __restrict__ out, int nrows) {
    int warp = threadIdx.x >> 5;
    int lane = threadIdx.x & 31;
    int row = blockIdx.x * WARPS_PER_BLOCK + warp;
    if (row >= nrows) return;

    const float* __restrict__ xr = x + (size_t)row * D;
    float* __restrict__ orow = out + (size_t)row * D;

    // 512 floats = 64 chunks of 8; 32 lanes * 2 chunks, front-batched.
    f8 a = ldg256(xr + lane * 8);
    f8 b = ldg256(xr + 256 + lane * 8);

    float s = ((a.v[0] + a.v[1]) + (a.v[2] + a.v[3]))
            + ((a.v[4] + a.v[5]) + (a.v[6] + a.v[7]))
            + ((b.v[0] + b.v[1]) + (b.v[2] + b.v[3]))
            + ((b.v[4] + b.v[5]) + (b.v[6] + b.v[7]));

    #pragma unroll
    for (int off = 16; off > 0; off >>= 1)
        s += __shfl_xor_sync(0xffffffffu, s, off);

    #pragma unroll
    for (int i = 0; i < 8; i++) { a.v[i] -= s; b.v[i] -= s; }

    stg256(orow + lane * 8, a);
    stg256(orow + 256 + lane * 8, b);
}

extern "C" void kernel_launch(void* const* d_in, const int* in_sizes, int n_in,
                              void* d_out, int out_size) {
    const float* x = (const float*)d_in[0];
    float* out = (float*)d_out;
    int nrows = in_sizes[0] / D;
    int blocks = (nrows + WARPS_PER_BLOCK - 1) / WARPS_PER_BLOCK;
    neg_sum_add_kernel<<<blocks, WARPS_PER_BLOCK * 32>>>(x, out, nrows);
}

// round 13
// speedup vs baseline: 1.0338x; 1.0338x over previous
#include <cuda_runtime.h>

// out[row, :] = x[row, :] - sum(x[row, :])
// x: [R, 512] fp32, R = 8*8192 = 65536. HBM-bound (268 MB stream, ~7.5 TB/s
// effective). Final form: one warp per row, 256-thr blocks (best measured grid
// shape), 256-bit vector loads/stores (2 LDG.256 + 2 STG.256 per lane = minimal
// LSU issue count). L2 eviction hints measured neutral -> omitted.

static constexpr int D = 512;
static constexpr int WARPS_PER_BLOCK = 8;

struct f8 { float v[8]; };

__device__ __forceinline__ f8 ldg256(const float* p) {
    f8 r;
    asm volatile(
        "ld.global.v8.b32 {%0,%1,%2,%3,%4,%5,%6,%7}, [%8];"
        : "=f"(r.v[0]), "=f"(r.v[1]), "=f"(r.v[2]), "=f"(r.v[3]),
          "=f"(r.v[4]), "=f"(r.v[5]), "=f"(r.v[6]), "=f"(r.v[7])
        : "l"(p));
    return r;
}

__device__ __forceinline__ void stg256(float* p, const f8& r) {
    asm volatile(
        "st.global.v8.b32 [%0], {%1,%2,%3,%4,%5,%6,%7,%8};"
        :: "l"(p),
           "f"(r.v[0]), "f"(r.v[1]), "f"(r.v[2]), "f"(r.v[3]),
           "f"(r.v[4]), "f"(r.v[5]), "f"(r.v[6]), "f"(r.v[7])
        : "memory");
}

__global__ void __launch_bounds__(WARPS_PER_BLOCK * 32)
neg_sum_add_kernel(const float* __restrict__ x, float* __restrict__ out, int nrows) {
    int warp = threadIdx.x >> 5;
    int lane = threadIdx.x & 31;
    int row = blockIdx.x * WARPS_PER_BLOCK + warp;
    if (row >= nrows) return;

    const float* __restrict__ xr = x + (size_t)row * D;
    float* __restrict__ orow = out + (size_t)row * D;

    // 512 floats = 64 chunks of 8; 32 lanes * 2 chunks, front-batched.
    f8 a = ldg256(xr + lane * 8);
    f8 b = ldg256(xr + 256 + lane * 8);

    float s = ((a.v[0] + a.v[1]) + (a.v[2] + a.v[3]))
            + ((a.v[4] + a.v[5]) + (a.v[6] + a.v[7]))
            + ((b.v[0] + b.v[1]) + (b.v[2] + b.v[3]))
            + ((b.v[4] + b.v[5]) + (b.v[6] + b.v[7]));

    #pragma unroll
    for (int off = 16; off > 0; off >>= 1)
        s += __shfl_xor_sync(0xffffffffu, s, off);

    #pragma unroll
    for (int i = 0; i < 8; i++) { a.v[i] -= s; b.v[i] -= s; }

    stg256(orow + lane * 8, a);
    stg256(orow + 256 + lane * 8, b);
}

extern "C" void kernel_launch(void* const* d_in, const int* in_sizes, int n_in,
                              void* d_out, int out_size) {
    const float* x = (const float*)d_in[0];
    float* out = (float*)d_out;
    int nrows = in_sizes[0] / D;
    int blocks = (nrows + WARPS_PER_BLOCK - 1) / WARPS_PER_BLOCK;
    neg_sum_add_kernel<<<blocks, WARPS_PER_BLOCK * 32>>>(x, out, nrows);
}